// round 5
// baseline (speedup 1.0000x reference)
#include <cuda_runtime.h>

// Problem dims
#define B_   64
#define T_   96
#define F_   32
#define H_   128
#define HS4  512      // 4*H
#define NTH  512

// ---- shared memory layout (float offsets) ----
#define OFF_XIN    0          // 3072   : inputs[b] as [t][f]
#define OFF_XENC   3072       // 12384  : x_encoded [96][129] (padded stride)
#define XENC_S     129
#define OFF_XDPRE  15456      // 12288  : decoder attention precompute [96][128]
#define OFF_U      27744      // 16384  : union scratch
#define OFF_WTMP   OFF_U              // 12288 : ae_w1 rows 256..351 (96x128)
#define OFF_XEPRE  (OFF_U + 12288)    // 4096  : encoder attention precompute [32][128]
#define OFF_WBUF   OFF_U              // 16384 : ad_w1 rows 256..383 (128x128)
#define OFF_HS     44128      // 256   : [h | s]  (enc)  /  [d | c] (dec)
#define OFF_A      44384      // 128   : attention hidden pre-activation
#define OFF_RED    44512      // 2048  : cross-warp reduction scratch
#define OFF_EW     46560      // 96    : attention logits
#define OFF_BETA   46656      // 96    : decoder attention weights
#define OFF_XT     46752      // 32    : alpha * x_t
#define OFF_CTX    46784      // 128   : context vector
#define OFF_YT     46912      // 128   : y_tilde
#define OFF_W2     47040      // 128   : ae_w2 / ad_w2 cache
#define OFF_B1     47168      // 128   : ae_b1 / ad_b1 cache
#define SMEM_F     47296
#define SMEM_BYTES (SMEM_F * 4)       // 189184 bytes

__device__ __forceinline__ float tanh_f(float x) {
    // tanh = 1 - 2/(exp(2x)+1); __expf+__fdividef: ~1e-6 rel err, 2 MUFU
    float e = __expf(2.0f * x);
    return 1.0f - __fdividef(2.0f, e + 1.0f);
}
__device__ __forceinline__ float sig_f(float x) {
    return __fdividef(1.0f, 1.0f + __expf(-x));
}
__device__ __forceinline__ void fma4(float4& a, float s, const float4 w) {
    a.x = fmaf(s, w.x, a.x); a.y = fmaf(s, w.y, a.y);
    a.z = fmaf(s, w.z, a.z); a.w = fmaf(s, w.w, a.w);
}

extern __shared__ float sm[];

__global__ void __launch_bounds__(NTH, 1)
darnn_kernel(const float* __restrict__ inputs,
             const float* __restrict__ enc_k, const float* __restrict__ enc_r,
             const float* __restrict__ enc_b,
             const float* __restrict__ ae_w1, const float* __restrict__ ae_b1,
             const float* __restrict__ ae_w2, const float* __restrict__ ae_b2,
             const float* __restrict__ dec_k, const float* __restrict__ dec_r,
             const float* __restrict__ dec_b,
             const float* __restrict__ ad_w1, const float* __restrict__ ad_b1,
             const float* __restrict__ ad_w2, const float* __restrict__ ad_b2,
             const float* __restrict__ fc_w, const float* __restrict__ fc_b,
             const float* __restrict__ ff_w, const float* __restrict__ ff_b,
             float* __restrict__ out)
{
    const int tid = threadIdx.x;
    const int b   = blockIdx.x;

    float* xin   = sm + OFF_XIN;
    float* xenc  = sm + OFF_XENC;
    float* xdpre = sm + OFF_XDPRE;
    float* wtmp  = sm + OFF_WTMP;
    float* xepre = sm + OFF_XEPRE;
    float* wbuf  = sm + OFF_WBUF;
    float* hs    = sm + OFF_HS;
    float* aw    = sm + OFF_A;
    float* red   = sm + OFF_RED;
    float* ew    = sm + OFF_EW;
    float* beta  = sm + OFF_BETA;
    float* xt    = sm + OFF_XT;
    float* ctx   = sm + OFF_CTX;
    float* yt    = sm + OFF_YT;
    float* w2c   = sm + OFF_W2;
    float* b1c   = sm + OFF_B1;

    // ---------- Phase 0: stage inputs + encoder-attention constants ----------
    for (int i = tid; i < T_ * F_; i += NTH) xin[i] = inputs[b * T_ * F_ + i];
    for (int i = tid; i < T_ * H_; i += NTH) wtmp[i] = ae_w1[256 * H_ + i];  // x-rows of ae_w1
    if (tid < H_)   { w2c[tid] = ae_w2[tid]; b1c[tid] = ae_b1[tid]; }
    if (tid < 2*H_) hs[tid] = 0.0f;
    __syncthreads();

    // xe_pre[f][j] = sum_t x[t][f] * ae_w1[2H+t][j]   (step-invariant hoist)
    for (int slot = tid; slot < F_ * (H_ / 4); slot += NTH) {   // 1024 slots
        int f = slot >> 5, jq = slot & 31;
        float4 acc = make_float4(0.f, 0.f, 0.f, 0.f);
        for (int t = 0; t < T_; ++t) {
            float xv = xin[t * F_ + f];
            float4 w = reinterpret_cast<const float4*>(wtmp + t * H_)[jq];
            fma4(acc, xv, w);
        }
        reinterpret_cast<float4*>(xepre + f * H_)[jq] = acc;
    }
    __syncthreads();

    // ---------- Phase 1: encoder (96 sequential steps) ----------
    for (int t = 0; t < T_; ++t) {
        // a[j] = ae_b1[j] + [h|s] @ ae_w1[0:256]   (16 k-parts x 16 rows)
        {
            int jq = tid & 31, part = tid >> 5;
            float4 acc = make_float4(0.f, 0.f, 0.f, 0.f);
            int k0 = part * 16;
            #pragma unroll
            for (int k = k0; k < k0 + 16; ++k) {
                float hv = hs[k];
                float4 w = reinterpret_cast<const float4*>(ae_w1 + k * H_)[jq];
                fma4(acc, hv, w);
            }
            reinterpret_cast<float4*>(red + part * H_)[jq] = acc;
        }
        __syncthreads();
        if (tid < H_) {
            float acc = b1c[tid];
            #pragma unroll
            for (int p = 0; p < 16; ++p) acc += red[p * H_ + tid];
            aw[tid] = acc;
        }
        __syncthreads();

        // e[f] = sum_j tanh(xe_pre[f][j] + a[j]) * ae_w2[j]   (b2 cancels in softmax)
        {
            int f = tid >> 4, sub = tid & 15;
            float acc = 0.f;
            int j0 = sub * 8;
            #pragma unroll
            for (int j = j0; j < j0 + 8; ++j)
                acc += tanh_f(xepre[f * H_ + j] + aw[j]) * w2c[j];
            acc += __shfl_down_sync(0xffffffffu, acc, 8);
            acc += __shfl_down_sync(0xffffffffu, acc, 4);
            acc += __shfl_down_sync(0xffffffffu, acc, 2);
            acc += __shfl_down_sync(0xffffffffu, acc, 1);
            if (sub == 0) ew[f] = acc;
        }
        __syncthreads();

        // softmax over F=32 + x_tilde
        if (tid < 32) {
            float v = ew[tid], m = v;
            #pragma unroll
            for (int o = 16; o; o >>= 1) m = fmaxf(m, __shfl_xor_sync(0xffffffffu, m, o));
            float p = __expf(v - m), s = p;
            #pragma unroll
            for (int o = 16; o; o >>= 1) s += __shfl_xor_sync(0xffffffffu, s, o);
            xt[tid] = __fdividef(p, s) * xin[t * F_ + tid];
        }
        __syncthreads();

        // gates z[g] = enc_b + x_tilde@enc_k + h@enc_r   (4 row-parts x 40 rows)
        {
            int gq = tid & 127, part = tid >> 7;
            float4 acc = make_float4(0.f, 0.f, 0.f, 0.f);
            int r0 = part * 40;
            #pragma unroll 8
            for (int r = r0; r < r0 + 40; ++r) {
                float v; const float* Wrow;
                if (r < 32) { v = xt[r];      Wrow = enc_k + r * HS4; }
                else        { v = hs[r - 32]; Wrow = enc_r + (r - 32) * HS4; }
                float4 w = reinterpret_cast<const float4*>(Wrow)[gq];
                fma4(acc, v, w);
            }
            reinterpret_cast<float4*>(red + part * HS4)[gq] = acc;
        }
        __syncthreads();
        if (tid < H_) {
            int j = tid;
            float z0 = enc_b[j], z1 = enc_b[H_ + j], z2 = enc_b[2*H_ + j], z3 = enc_b[3*H_ + j];
            #pragma unroll
            for (int p = 0; p < 4; ++p) {
                z0 += red[p * HS4 + j];
                z1 += red[p * HS4 + H_ + j];
                z2 += red[p * HS4 + 2*H_ + j];
                z3 += red[p * HS4 + 3*H_ + j];
            }
            float ig = sig_f(z0), fg = sig_f(z1), gg = tanh_f(z2), og = sig_f(z3);
            float c = fg * hs[H_ + j] + ig * gg;
            float h = og * tanh_f(c);
            hs[j] = h; hs[H_ + j] = c;
            xenc[t * XENC_S + j] = h;
        }
        __syncthreads();
    }

    // ---------- Phase 2: decoder-attention constants + hoist ----------
    for (int i = tid; i < H_ * H_; i += NTH) wbuf[i] = ad_w1[256 * H_ + i];  // x-rows of ad_w1
    if (tid < H_)   { w2c[tid] = ad_w2[tid]; b1c[tid] = ad_b1[tid]; }
    if (tid < 2*H_) hs[tid] = 0.0f;   // d, c
    __syncthreads();

    // xd_pre[tt][j] = sum_k x_enc[tt][k] * ad_w1[2H+k][j]
    for (int slot = tid; slot < T_ * (H_ / 4); slot += NTH) {   // 3072 slots
        int tt = slot >> 5, jq = slot & 31;
        float4 acc = make_float4(0.f, 0.f, 0.f, 0.f);
        for (int k = 0; k < H_; ++k) {
            float xv = xenc[tt * XENC_S + k];
            float4 w = reinterpret_cast<const float4*>(wbuf + k * H_)[jq];
            fma4(acc, xv, w);
        }
        reinterpret_cast<float4*>(xdpre + tt * H_)[jq] = acc;
    }
    __syncthreads();

    // ---------- Phase 3: decoder (96 sequential steps) ----------
    for (int t = 0; t < T_; ++t) {
        // a[j] = ad_b1[j] + [d|c] @ ad_w1[0:256]
        {
            int jq = tid & 31, part = tid >> 5;
            float4 acc = make_float4(0.f, 0.f, 0.f, 0.f);
            int k0 = part * 16;
            #pragma unroll
            for (int k = k0; k < k0 + 16; ++k) {
                float hv = hs[k];
                float4 w = reinterpret_cast<const float4*>(ad_w1 + k * H_)[jq];
                fma4(acc, hv, w);
            }
            reinterpret_cast<float4*>(red + part * H_)[jq] = acc;
        }
        __syncthreads();
        if (tid < H_) {
            float acc = b1c[tid];
            #pragma unroll
            for (int p = 0; p < 16; ++p) acc += red[p * H_ + tid];
            aw[tid] = acc;
        }
        __syncthreads();

        // e[tt] = sum_j tanh(xd_pre[tt][j] + a[j]) * ad_w2[j]
        if (tid < 384) {
            int tt = tid >> 2, sub = tid & 3;
            float acc = 0.f;
            int j0 = sub * 32;
            #pragma unroll 8
            for (int j = j0; j < j0 + 32; ++j)
                acc += tanh_f(xdpre[tt * H_ + j] + aw[j]) * w2c[j];
            acc += __shfl_down_sync(0xffffffffu, acc, 2);
            acc += __shfl_down_sync(0xffffffffu, acc, 1);
            if (sub == 0) ew[tt] = acc;
        }
        __syncthreads();

        // softmax over T=96
        if (tid < 32) {
            float v0 = ew[tid], v1 = ew[tid + 32], v2 = ew[tid + 64];
            float m = fmaxf(v0, fmaxf(v1, v2));
            #pragma unroll
            for (int o = 16; o; o >>= 1) m = fmaxf(m, __shfl_xor_sync(0xffffffffu, m, o));
            float p0 = __expf(v0 - m), p1 = __expf(v1 - m), p2 = __expf(v2 - m);
            float s = p0 + p1 + p2;
            #pragma unroll
            for (int o = 16; o; o >>= 1) s += __shfl_xor_sync(0xffffffffu, s, o);
            float inv = __fdividef(1.0f, s);
            beta[tid] = p0 * inv; beta[tid + 32] = p1 * inv; beta[tid + 64] = p2 * inv;
        }
        __syncthreads();

        // ctx[k] = sum_tt beta[tt] * x_enc[tt][k]
        {
            int k = tid >> 2, sub = tid & 3;
            float acc = 0.f;
            int t0 = sub * 24;
            #pragma unroll 8
            for (int tt = t0; tt < t0 + 24; ++tt)
                acc += beta[tt] * xenc[tt * XENC_S + k];
            acc += __shfl_down_sync(0xffffffffu, acc, 2);
            acc += __shfl_down_sync(0xffffffffu, acc, 1);
            if (sub == 0) ctx[k] = acc;
        }
        __syncthreads();

        // y_tilde = [ctx, y_t] @ fc_w + fc_b   (16 parts x 8 rows; part0 adds y-row + bias)
        {
            int jq = tid & 31, part = tid >> 5;
            float4 acc = make_float4(0.f, 0.f, 0.f, 0.f);
            int r0 = part * 8;
            #pragma unroll
            for (int r = r0; r < r0 + 8; ++r) {
                float v = ctx[r];
                float4 w = reinterpret_cast<const float4*>(fc_w + r * H_)[jq];
                fma4(acc, v, w);
            }
            if (part == 0) {
                float yv = xin[t * F_ + (F_ - 1)];
                float4 w = reinterpret_cast<const float4*>(fc_w + H_ * H_)[jq];
                fma4(acc, yv, w);
                float4 bb = reinterpret_cast<const float4*>(fc_b)[jq];
                acc.x += bb.x; acc.y += bb.y; acc.z += bb.z; acc.w += bb.w;
            }
            reinterpret_cast<float4*>(red + part * H_)[jq] = acc;
        }
        __syncthreads();
        if (tid < H_) {
            float acc = 0.f;
            #pragma unroll
            for (int p = 0; p < 16; ++p) acc += red[p * H_ + tid];
            yt[tid] = acc;
        }
        __syncthreads();

        // gates z[g] = dec_b + y_tilde@dec_k + d@dec_r   (4 parts x 64 rows)
        {
            int gq = tid & 127, part = tid >> 7;
            float4 acc = make_float4(0.f, 0.f, 0.f, 0.f);
            int r0 = part * 64;
            #pragma unroll 8
            for (int r = r0; r < r0 + 64; ++r) {
                float v; const float* Wrow;
                if (r < 128) { v = yt[r];       Wrow = dec_k + r * HS4; }
                else         { v = hs[r - 128]; Wrow = dec_r + (r - 128) * HS4; }
                float4 w = reinterpret_cast<const float4*>(Wrow)[gq];
                fma4(acc, v, w);
            }
            reinterpret_cast<float4*>(red + part * HS4)[gq] = acc;
        }
        __syncthreads();
        if (tid < H_) {
            int j = tid;
            float z0 = dec_b[j], z1 = dec_b[H_ + j], z2 = dec_b[2*H_ + j], z3 = dec_b[3*H_ + j];
            #pragma unroll
            for (int p = 0; p < 4; ++p) {
                z0 += red[p * HS4 + j];
                z1 += red[p * HS4 + H_ + j];
                z2 += red[p * HS4 + 2*H_ + j];
                z3 += red[p * HS4 + 3*H_ + j];
            }
            float ig = sig_f(z0), fg = sig_f(z1), gg = tanh_f(z2), og = sig_f(z3);
            float c = fg * hs[H_ + j] + ig * gg;
            float d = og * tanh_f(c);
            hs[j] = d; hs[H_ + j] = c;
        }
        __syncthreads();
    }

    // ---------- Phase 4: output head  y = [d, ctx] @ ff_w + ff_b ----------
    if (tid < F_) {
        float acc = ff_b[tid];
        #pragma unroll 4
        for (int k = 0; k < H_; ++k) acc += hs[k] * ff_w[k * F_ + tid];
        #pragma unroll 4
        for (int k = 0; k < H_; ++k) acc += ctx[k] * ff_w[(H_ + k) * F_ + tid];
        out[b * F_ + tid] = acc;
    }
}

extern "C" void kernel_launch(void* const* d_in, const int* in_sizes, int n_in,
                              void* d_out, int out_size) {
    const float* inputs = (const float*)d_in[0];
    const float* enc_k  = (const float*)d_in[1];
    const float* enc_r  = (const float*)d_in[2];
    const float* enc_b  = (const float*)d_in[3];
    const float* ae_w1  = (const float*)d_in[4];
    const float* ae_b1  = (const float*)d_in[5];
    const float* ae_w2  = (const float*)d_in[6];
    const float* ae_b2  = (const float*)d_in[7];
    const float* dec_k  = (const float*)d_in[8];
    const float* dec_r  = (const float*)d_in[9];
    const float* dec_b  = (const float*)d_in[10];
    const float* ad_w1  = (const float*)d_in[11];
    const float* ad_b1  = (const float*)d_in[12];
    const float* ad_w2  = (const float*)d_in[13];
    const float* ad_b2  = (const float*)d_in[14];
    const float* fc_w   = (const float*)d_in[15];
    const float* fc_b   = (const float*)d_in[16];
    const float* ff_w   = (const float*)d_in[17];
    const float* ff_b   = (const float*)d_in[18];
    float* out = (float*)d_out;

    cudaFuncSetAttribute(darnn_kernel, cudaFuncAttributeMaxDynamicSharedMemorySize, SMEM_BYTES);
    darnn_kernel<<<B_, NTH, SMEM_BYTES>>>(inputs, enc_k, enc_r, enc_b,
                                          ae_w1, ae_b1, ae_w2, ae_b2,
                                          dec_k, dec_r, dec_b,
                                          ad_w1, ad_b1, ad_w2, ad_b2,
                                          fc_w, fc_b, ff_w, ff_b, out);
}